// round 4
// baseline (speedup 1.0000x reference)
#include <cuda_runtime.h>
#include <math.h>

#define N_ATOMS   8000
#define N_PAIRS   80000
#define NF        32          // nf_in == nf_out
#define ND        16          // n_dist
#define NC        4           // n_comp
#define SPAN      (ND * NF)   // 512
#define HARD_CUT  6.5f
#define GN_EPS    1e-5f

// ---------------- scratch (device globals; no allocation allowed) -----------
__device__ float g_proj[N_ATOMS * SPAN];    // proj[j][d*32+o]  (16.4 MB)
__device__ float g_h[N_PAIRS * NF];         // h[p][o]          (10.2 MB)

// ---------------- K1: proj[j,d,o] = sum_f feat[j,f] * W[d,o,f] --------------
// 512 threads: thread = d*32+o holds its 32 weights in registers.
// 16 atoms/block, 4 atoms per barrier phase; feat read as float4 from smem.
#define APB 16
__global__ __launch_bounds__(512) void proj_kernel(
        const float* __restrict__ feat,
        const float* __restrict__ intw) {
    int tid = threadIdx.x;
    float w[NF];
    const float4* wp = reinterpret_cast<const float4*>(intw + tid * NF);
#pragma unroll
    for (int k = 0; k < NF / 4; k++) {
        float4 v = wp[k];
        w[4 * k + 0] = v.x; w[4 * k + 1] = v.y;
        w[4 * k + 2] = v.z; w[4 * k + 3] = v.w;
    }
    __shared__ __align__(16) float fsh[4][NF];
    int a0 = blockIdx.x * APB;
#pragma unroll 1
    for (int it = 0; it < APB; it += 4) {
        if (tid < 128)
            fsh[tid >> 5][tid & 31] = feat[(a0 + it + (tid >> 5)) * NF + (tid & 31)];
        __syncthreads();
        const float4* f0 = reinterpret_cast<const float4*>(fsh[0]);
        const float4* f1 = reinterpret_cast<const float4*>(fsh[1]);
        const float4* f2 = reinterpret_cast<const float4*>(fsh[2]);
        const float4* f3 = reinterpret_cast<const float4*>(fsh[3]);
        float acc0 = 0.f, acc1 = 0.f, acc2 = 0.f, acc3 = 0.f;
#pragma unroll
        for (int q = 0; q < NF / 4; q++) {
            float4 v0 = f0[q], v1 = f1[q], v2 = f2[q], v3 = f3[q];
            float w0 = w[4 * q + 0], w1 = w[4 * q + 1];
            float w2 = w[4 * q + 2], w3 = w[4 * q + 3];
            acc0 = fmaf(w0, v0.x, acc0); acc0 = fmaf(w1, v0.y, acc0);
            acc0 = fmaf(w2, v0.z, acc0); acc0 = fmaf(w3, v0.w, acc0);
            acc1 = fmaf(w0, v1.x, acc1); acc1 = fmaf(w1, v1.y, acc1);
            acc1 = fmaf(w2, v1.z, acc1); acc1 = fmaf(w3, v1.w, acc1);
            acc2 = fmaf(w0, v2.x, acc2); acc2 = fmaf(w1, v2.y, acc2);
            acc2 = fmaf(w2, v2.z, acc2); acc2 = fmaf(w3, v2.w, acc2);
            acc3 = fmaf(w0, v3.x, acc3); acc3 = fmaf(w1, v3.y, acc3);
            acc3 = fmaf(w2, v3.z, acc3); acc3 = fmaf(w3, v3.w, acc3);
        }
        g_proj[(a0 + it + 0) * SPAN + tid] = acc0;
        g_proj[(a0 + it + 1) * SPAN + tid] = acc1;
        g_proj[(a0 + it + 2) * SPAN + tid] = acc2;
        g_proj[(a0 + it + 3) * SPAN + tid] = acc3;
        __syncthreads();
    }
}

// ---------------- K2: h[p,o] = sum_d sense[p,d] * proj[j_p,d,o] -------------
// One warp per pair; proj row read as 4x LDG.128 per warp.
// lane = dh*8 + og : dh = d-slice (0..3), og = output group (o = og*4..og*4+3)
__global__ __launch_bounds__(256) void hpair_kernel(
        const float* __restrict__ dist,
        const float* __restrict__ mu,
        const float* __restrict__ sigma,
        const int* __restrict__ pair_second) {
    int warp = threadIdx.x >> 5;
    int lane = threadIdx.x & 31;
    int p = blockIdx.x * 8 + warp;           // grid = N_PAIRS/8 exact

    float dp = dist[p];                       // uniform
    float sv = 0.0f;
    if (lane < ND) {
        float invd = 1.0f / dp;
        float z    = (invd - mu[lane]) / sigma[lane];
        float base = __expf(-0.5f * z * z);
        float c    = __cosf(0.24166097335f * dp);   // 0.5*pi/6.5
        float cut  = (dp < HARD_CUT) ? c * c : 0.0f;
        sv = base * cut;
    }
    int j = pair_second[p];                   // uniform
    const float4* pr4 = reinterpret_cast<const float4*>(g_proj + j * SPAN);

    int dh = lane >> 3;                       // 0..3
    float4 acc = make_float4(0.f, 0.f, 0.f, 0.f);
#pragma unroll
    for (int t = 0; t < 4; t++) {
        // idx = t*32 + lane : d = t*4 + dh, o-group = lane & 7
        float s = __shfl_sync(0xffffffffu, sv, t * 4 + dh);
        float4 v = pr4[t * 32 + lane];
        acc.x = fmaf(s, v.x, acc.x);
        acc.y = fmaf(s, v.y, acc.y);
        acc.z = fmaf(s, v.z, acc.z);
        acc.w = fmaf(s, v.w, acc.w);
    }
    // reduce over dh (lanes differing in bits 3,4)
#pragma unroll
    for (int m = 8; m <= 16; m <<= 1) {
        acc.x += __shfl_xor_sync(0xffffffffu, acc.x, m);
        acc.y += __shfl_xor_sync(0xffffffffu, acc.y, m);
        acc.z += __shfl_xor_sync(0xffffffffu, acc.z, m);
        acc.w += __shfl_xor_sync(0xffffffffu, acc.w, m);
    }
    if (lane < 8)
        reinterpret_cast<float4*>(g_h + p * NF)[lane] = acc;
}

// ---------------- K3: per-atom warp — pair loop + invariants + GN + mix -----
__global__ __launch_bounds__(256) void atom_kernel(
        const float* __restrict__ feat,
        const float* __restrict__ rhat,        // (P,4)
        const int*   __restrict__ pair_first,  // sorted
        const float* __restrict__ selfw,       // (32,32) [o][f]
        const float* __restrict__ selfb,       // (32)
        const float* __restrict__ mixw,        // (64,32) flat k*32+oo, k=o*2+g
        const float* __restrict__ gnw,         // (64) [g*32+o]
        const float* __restrict__ gnb,
        float* __restrict__ out) {
    __shared__ float swsh[NF * NF];            // selfint_w transposed [f*32+o]
    __shared__ float xn_sh[8][64];

    for (int i = threadIdx.x; i < NF * NF; i += 256)
        swsh[i] = selfw[(i & 31) * NF + (i >> 5)];
    __syncthreads();

    int warp = threadIdx.x >> 5;
    int lane = threadIdx.x & 31;
    int a = blockIdx.x * 8 + warp;

    // fused segment search: lanes 0/1 find lower_bound(a), lower_bound(a+1)
    int target = a + (lane & 1);
    int lo = 0, hi = N_PAIRS;
    while (lo < hi) {
        int mid = (lo + hi) >> 1;
        if (pair_first[mid] < target) lo = mid + 1; else hi = mid;
    }
    int p0 = __shfl_sync(0xffffffffu, lo, 0);
    int p1 = __shfl_sync(0xffffffffu, lo, 1);

    float tf0 = 0.f, tf1 = 0.f, tf2 = 0.f, tf3 = 0.f;
    int p = p0;
    for (; p + 1 < p1; p += 2) {
        float ha = g_h[p * NF + lane];
        float hb = g_h[(p + 1) * NF + lane];
        const float4 ra = *reinterpret_cast<const float4*>(rhat + p * NC);
        const float4 rb = *reinterpret_cast<const float4*>(rhat + (p + 1) * NC);
        tf0 = fmaf(ra.x, ha, tf0); tf0 = fmaf(rb.x, hb, tf0);
        tf1 = fmaf(ra.y, ha, tf1); tf1 = fmaf(rb.y, hb, tf1);
        tf2 = fmaf(ra.z, ha, tf2); tf2 = fmaf(rb.z, hb, tf2);
        tf3 = fmaf(ra.w, ha, tf3); tf3 = fmaf(rb.w, hb, tf3);
    }
    if (p < p1) {
        float ha = g_h[p * NF + lane];
        const float4 ra = *reinterpret_cast<const float4*>(rhat + p * NC);
        tf0 = fmaf(ra.x, ha, tf0);
        tf1 = fmaf(ra.y, ha, tf1);
        tf2 = fmaf(ra.z, ha, tf2);
        tf3 = fmaf(ra.w, ha, tf3);
    }

    // invariants
    float inv0 = tf0;
    float inv1 = tf1 * tf1 + tf2 * tf2 + tf3 * tf3;

    // GroupNorm across the warp's 32 lanes (channels)
    float xn0, xn1;
    {
        float s = inv0, sq = inv0 * inv0;
#pragma unroll
        for (int m = 16; m; m >>= 1) {
            s  += __shfl_xor_sync(0xffffffffu, s,  m);
            sq += __shfl_xor_sync(0xffffffffu, sq, m);
        }
        float mean = s * (1.0f / 32.0f);
        float var  = sq * (1.0f / 32.0f) - mean * mean;
        xn0 = (inv0 - mean) * rsqrtf(var + GN_EPS) * gnw[lane] + gnb[lane];
    }
    {
        float s = inv1, sq = inv1 * inv1;
#pragma unroll
        for (int m = 16; m; m >>= 1) {
            s  += __shfl_xor_sync(0xffffffffu, s,  m);
            sq += __shfl_xor_sync(0xffffffffu, sq, m);
        }
        float mean = s * (1.0f / 32.0f);
        float var  = sq * (1.0f / 32.0f) - mean * mean;
        xn1 = (inv1 - mean) * rsqrtf(var + GN_EPS) * gnw[NF + lane] + gnb[NF + lane];
    }
    // norm_inv layout: k = o*2 + g
    xn_sh[warp][lane * 2 + 0] = xn0;
    xn_sh[warp][lane * 2 + 1] = xn1;
    __syncwarp();

    // mixing GEMV
    float m = 0.f;
#pragma unroll
    for (int k = 0; k < 2 * NF; k++)
        m = fmaf(xn_sh[warp][k], mixw[k * NF + lane], m);

    // self interaction
    float sp = selfb[lane];
    const float* fa = feat + a * NF;
#pragma unroll
    for (int f = 0; f < NF; f++)
        sp = fmaf(fa[f], swsh[f * NF + lane], sp);

    out[a * NF + lane] = m + sp;
}

// ---------------- launch ----------------------------------------------------
extern "C" void kernel_launch(void* const* d_in, const int* in_sizes, int n_in,
                              void* d_out, int out_size) {
    const float* in_features    = (const float*)d_in[0];
    const float* tensor_rhats   = (const float*)d_in[1];
    const float* dist_pairs     = (const float*)d_in[2];
    const float* int_weights    = (const float*)d_in[3];
    const float* selfint_w      = (const float*)d_in[4];
    const float* selfint_b      = (const float*)d_in[5];
    const float* mixing_weights = (const float*)d_in[6];
    const float* gn_weight      = (const float*)d_in[7];
    const float* gn_bias        = (const float*)d_in[8];
    const float* sens_mu        = (const float*)d_in[9];
    const float* sens_sigma     = (const float*)d_in[10];
    const int*   pair_first     = (const int*)d_in[11];
    const int*   pair_second    = (const int*)d_in[12];
    float* out = (float*)d_out;

    proj_kernel<<<N_ATOMS / APB, 512>>>(in_features, int_weights);
    hpair_kernel<<<N_PAIRS / 8, 256>>>(dist_pairs, sens_mu, sens_sigma, pair_second);
    atom_kernel<<<N_ATOMS / 8, 256>>>(in_features, tensor_rhats, pair_first,
                                      selfint_w, selfint_b, mixing_weights,
                                      gn_weight, gn_bias, out);
}

// round 5
// speedup vs baseline: 1.0309x; 1.0309x over previous
#include <cuda_runtime.h>
#include <cuda_fp16.h>
#include <math.h>

#define N_ATOMS   8000
#define N_PAIRS   80000
#define NF        32          // nf_in == nf_out
#define ND        16          // n_dist
#define NC        4           // n_comp
#define SPAN      (ND * NF)   // 512
#define HARD_CUT  6.5f
#define GN_EPS    1e-5f

// ---------------- scratch (device globals; no allocation allowed) -----------
__device__ __half g_projh[N_ATOMS * SPAN];  // proj[j][d*32+o] fp16 (8.2 MB)
__device__ float  g_h[N_PAIRS * NF];        // h[p][o]              (10.2 MB)

// packed f32x2 helpers (Blackwell FFMA2 — only reachable via PTX)
__device__ __forceinline__ unsigned long long pack_f32x2(float lo, float hi) {
    unsigned long long r;
    asm("mov.b64 %0, {%1, %2};" : "=l"(r) : "f"(lo), "f"(hi));
    return r;
}
__device__ __forceinline__ void unpack_f32x2(float& lo, float& hi, unsigned long long v) {
    asm("mov.b64 {%0, %1}, %2;" : "=f"(lo), "=f"(hi) : "l"(v));
}
__device__ __forceinline__ unsigned long long ffma2(unsigned long long a,
                                                    unsigned long long b,
                                                    unsigned long long c) {
    unsigned long long d;
    asm("fma.rn.f32x2 %0, %1, %2, %3;" : "=l"(d) : "l"(a), "l"(b), "l"(c));
    return d;
}

// ---------------- K1: proj[j,d,o] = sum_f feat[j,f] * W[d,o,f] --------------
// 512 threads: thread = d*32+o holds its 32 weights in registers.
// 16 atoms/block, ONE load phase + ONE barrier, FFMA2 over atom pairs.
#define APB 16
__global__ __launch_bounds__(512) void proj_kernel(
        const float* __restrict__ feat,
        const float* __restrict__ intw) {
    int tid = threadIdx.x;
    float w[NF];
    const float4* wp = reinterpret_cast<const float4*>(intw + tid * NF);
#pragma unroll
    for (int k = 0; k < NF / 4; k++) {
        float4 v = wp[k];
        w[4 * k + 0] = v.x; w[4 * k + 1] = v.y;
        w[4 * k + 2] = v.z; w[4 * k + 3] = v.w;
    }
    // fshT[f][a]: transposed features, stride 20 (16B-aligned float4 groups)
    __shared__ __align__(16) float fshT[NF][20];
    int a0 = blockIdx.x * APB;
    {
        int a = tid >> 5, f = tid & 31;
        fshT[f][a] = feat[(a0 + a) * NF + f];     // coalesced LDG
    }
    __syncthreads();

    unsigned long long acc[8];                     // 8 f32x2 = 16 atom accs
#pragma unroll
    for (int k = 0; k < 8; k++) acc[k] = 0ull;     // bits of (0.f,0.f)

#pragma unroll
    for (int f = 0; f < NF; f++) {
        unsigned long long w2 = pack_f32x2(w[f], w[f]);
        const float4* row = reinterpret_cast<const float4*>(fshT[f]);
#pragma unroll
        for (int q = 0; q < 4; q++) {              // atoms 4q..4q+3
            float4 v = row[q];                     // smem broadcast
            acc[2 * q + 0] = ffma2(w2, pack_f32x2(v.x, v.y), acc[2 * q + 0]);
            acc[2 * q + 1] = ffma2(w2, pack_f32x2(v.z, v.w), acc[2 * q + 1]);
        }
    }
#pragma unroll
    for (int k = 0; k < 8; k++) {
        float lo, hi;
        unpack_f32x2(lo, hi, acc[k]);
        g_projh[(a0 + 2 * k + 0) * SPAN + tid] = __float2half_rn(lo);
        g_projh[(a0 + 2 * k + 1) * SPAN + tid] = __float2half_rn(hi);
    }
}

// ---------------- K2: h[p,o] = sum_d sense[p,d] * proj_h[j_p,d,o] -----------
// One warp per pair; proj row (1KB fp16) read as 2x LDG.128 per warp.
// half idx = (t*32+lane)*8+e  ->  d = t*8 + lane/4,  o = (lane&3)*8 + e
__global__ __launch_bounds__(256) void hpair_kernel(
        const float* __restrict__ dist,
        const float* __restrict__ mu,
        const float* __restrict__ sigma,
        const int* __restrict__ pair_second) {
    int warp = threadIdx.x >> 5;
    int lane = threadIdx.x & 31;
    int p = blockIdx.x * 8 + warp;               // grid = N_PAIRS/8 exact

    float dp = dist[p];                           // uniform per warp
    float sv = 0.0f;
    if (lane < ND) {
        float invd = 1.0f / dp;
        float z    = (invd - mu[lane]) / sigma[lane];
        float base = __expf(-0.5f * z * z);
        float c    = __cosf(0.24166097335f * dp); // 0.5*pi/6.5
        float cut  = (dp < HARD_CUT) ? c * c : 0.0f;
        sv = base * cut;
    }
    int j = pair_second[p];                       // uniform
    const uint4* pr = reinterpret_cast<const uint4*>(g_projh + j * SPAN);

    float acc[8];
#pragma unroll
    for (int k = 0; k < 8; k++) acc[k] = 0.0f;

#pragma unroll
    for (int t = 0; t < 2; t++) {
        uint4 v = pr[t * 32 + lane];              // 8 halves
        float s = __shfl_sync(0xffffffffu, sv, t * 8 + (lane >> 2));
        const __half2* hv = reinterpret_cast<const __half2*>(&v);
        float2 c0 = __half22float2(hv[0]);
        float2 c1 = __half22float2(hv[1]);
        float2 c2 = __half22float2(hv[2]);
        float2 c3 = __half22float2(hv[3]);
        acc[0] = fmaf(s, c0.x, acc[0]); acc[1] = fmaf(s, c0.y, acc[1]);
        acc[2] = fmaf(s, c1.x, acc[2]); acc[3] = fmaf(s, c1.y, acc[3]);
        acc[4] = fmaf(s, c2.x, acc[4]); acc[5] = fmaf(s, c2.y, acc[5]);
        acc[6] = fmaf(s, c3.x, acc[6]); acc[7] = fmaf(s, c3.y, acc[7]);
    }
    // reduce over the 8 lanes sharing (lane & 3)
#pragma unroll
    for (int m = 4; m <= 16; m <<= 1) {
#pragma unroll
        for (int k = 0; k < 8; k++)
            acc[k] += __shfl_xor_sync(0xffffffffu, acc[k], m);
    }
    if (lane < 4) {
        float4 o0 = make_float4(acc[0], acc[1], acc[2], acc[3]);
        float4 o1 = make_float4(acc[4], acc[5], acc[6], acc[7]);
        float4* dst = reinterpret_cast<float4*>(g_h + p * NF + lane * 8);
        dst[0] = o0;
        dst[1] = o1;
    }
}

// ---------------- K3: per-atom warp — pair loop + invariants + GN + mix -----
__global__ __launch_bounds__(256) void atom_kernel(
        const float* __restrict__ feat,
        const float* __restrict__ rhat,        // (P,4)
        const int*   __restrict__ pair_first,  // sorted
        const float* __restrict__ selfw,       // (32,32) [o][f]
        const float* __restrict__ selfb,       // (32)
        const float* __restrict__ mixw,        // (64,32) flat k*32+oo, k=o*2+g
        const float* __restrict__ gnw,         // (64) [g*32+o]
        const float* __restrict__ gnb,
        float* __restrict__ out) {
    __shared__ float swsh[NF * NF];            // selfint_w transposed [f*32+o]
    __shared__ float xn_sh[8][64];

    for (int i = threadIdx.x; i < NF * NF; i += 256)
        swsh[i] = selfw[(i & 31) * NF + (i >> 5)];
    __syncthreads();

    int warp = threadIdx.x >> 5;
    int lane = threadIdx.x & 31;
    int a = blockIdx.x * 8 + warp;

    // fused segment search: lanes 0/1 find lower_bound(a), lower_bound(a+1)
    int target = a + (lane & 1);
    int lo = 0, hi = N_PAIRS;
    while (lo < hi) {
        int mid = (lo + hi) >> 1;
        if (pair_first[mid] < target) lo = mid + 1; else hi = mid;
    }
    int p0 = __shfl_sync(0xffffffffu, lo, 0);
    int p1 = __shfl_sync(0xffffffffu, lo, 1);

    float tf0 = 0.f, tf1 = 0.f, tf2 = 0.f, tf3 = 0.f;
    int p = p0;
    for (; p + 1 < p1; p += 2) {
        float ha = g_h[p * NF + lane];
        float hb = g_h[(p + 1) * NF + lane];
        const float4 ra = *reinterpret_cast<const float4*>(rhat + p * NC);
        const float4 rb = *reinterpret_cast<const float4*>(rhat + (p + 1) * NC);
        tf0 = fmaf(ra.x, ha, tf0); tf0 = fmaf(rb.x, hb, tf0);
        tf1 = fmaf(ra.y, ha, tf1); tf1 = fmaf(rb.y, hb, tf1);
        tf2 = fmaf(ra.z, ha, tf2); tf2 = fmaf(rb.z, hb, tf2);
        tf3 = fmaf(ra.w, ha, tf3); tf3 = fmaf(rb.w, hb, tf3);
    }
    if (p < p1) {
        float ha = g_h[p * NF + lane];
        const float4 ra = *reinterpret_cast<const float4*>(rhat + p * NC);
        tf0 = fmaf(ra.x, ha, tf0);
        tf1 = fmaf(ra.y, ha, tf1);
        tf2 = fmaf(ra.z, ha, tf2);
        tf3 = fmaf(ra.w, ha, tf3);
    }

    // invariants
    float inv0 = tf0;
    float inv1 = tf1 * tf1 + tf2 * tf2 + tf3 * tf3;

    // GroupNorm across the warp's 32 lanes (channels)
    float xn0, xn1;
    {
        float s = inv0, sq = inv0 * inv0;
#pragma unroll
        for (int m = 16; m; m >>= 1) {
            s  += __shfl_xor_sync(0xffffffffu, s,  m);
            sq += __shfl_xor_sync(0xffffffffu, sq, m);
        }
        float mean = s * (1.0f / 32.0f);
        float var  = sq * (1.0f / 32.0f) - mean * mean;
        xn0 = (inv0 - mean) * rsqrtf(var + GN_EPS) * gnw[lane] + gnb[lane];
    }
    {
        float s = inv1, sq = inv1 * inv1;
#pragma unroll
        for (int m = 16; m; m >>= 1) {
            s  += __shfl_xor_sync(0xffffffffu, s,  m);
            sq += __shfl_xor_sync(0xffffffffu, sq, m);
        }
        float mean = s * (1.0f / 32.0f);
        float var  = sq * (1.0f / 32.0f) - mean * mean;
        xn1 = (inv1 - mean) * rsqrtf(var + GN_EPS) * gnw[NF + lane] + gnb[NF + lane];
    }
    // norm_inv layout: k = o*2 + g
    xn_sh[warp][lane * 2 + 0] = xn0;
    xn_sh[warp][lane * 2 + 1] = xn1;
    __syncwarp();

    // mixing GEMV
    float m = 0.f;
#pragma unroll
    for (int k = 0; k < 2 * NF; k++)
        m = fmaf(xn_sh[warp][k], mixw[k * NF + lane], m);

    // self interaction
    float sp = selfb[lane];
    const float* fa = feat + a * NF;
#pragma unroll
    for (int f = 0; f < NF; f++)
        sp = fmaf(fa[f], swsh[f * NF + lane], sp);

    out[a * NF + lane] = m + sp;
}

// ---------------- launch ----------------------------------------------------
extern "C" void kernel_launch(void* const* d_in, const int* in_sizes, int n_in,
                              void* d_out, int out_size) {
    const float* in_features    = (const float*)d_in[0];
    const float* tensor_rhats   = (const float*)d_in[1];
    const float* dist_pairs     = (const float*)d_in[2];
    const float* int_weights    = (const float*)d_in[3];
    const float* selfint_w      = (const float*)d_in[4];
    const float* selfint_b      = (const float*)d_in[5];
    const float* mixing_weights = (const float*)d_in[6];
    const float* gn_weight      = (const float*)d_in[7];
    const float* gn_bias        = (const float*)d_in[8];
    const float* sens_mu        = (const float*)d_in[9];
    const float* sens_sigma     = (const float*)d_in[10];
    const int*   pair_first     = (const int*)d_in[11];
    const int*   pair_second    = (const int*)d_in[12];
    float* out = (float*)d_out;

    proj_kernel<<<N_ATOMS / APB, 512>>>(in_features, int_weights);
    hpair_kernel<<<N_PAIRS / 8, 256>>>(dist_pairs, sens_mu, sens_sigma, pair_second);
    atom_kernel<<<N_ATOMS / 8, 256>>>(in_features, tensor_rhats, pair_first,
                                      selfint_w, selfint_b, mixing_weights,
                                      gn_weight, gn_bias, out);
}

// round 9
// speedup vs baseline: 1.1163x; 1.0829x over previous
#include <cuda_runtime.h>
#include <cuda_fp16.h>
#include <math.h>

#define N_ATOMS   8000
#define N_PAIRS   80000
#define NF        32          // nf_in == nf_out
#define ND        16          // n_dist
#define NC        4           // n_comp
#define SPAN      (ND * NF)   // 512 halves per atom row
#define HARD_CUT  6.5f
#define GN_EPS    1e-5f

// scratch: proj[j][o][d] fp16, o-major (8.2 MB, L2-resident)
__device__ __half g_projh[N_ATOMS * SPAN];

union U2  { unsigned long long u; float2 f; };
union F4U { float4 f4; unsigned long long u[2]; };

__device__ __forceinline__ unsigned long long ffma2(unsigned long long a,
                                                    unsigned long long b,
                                                    unsigned long long c) {
    unsigned long long d;
    asm("fma.rn.f32x2 %0, %1, %2, %3;" : "=l"(d) : "l"(a), "l"(b), "l"(c));
    return d;
}

// ---------------- K1: proj[j][o][d] = sum_f feat[j,f] * W[d,o,f] ------------
// 512 threads: t -> (o = t>>4, d = t&15). 16 atoms/block, one barrier pair.
#define APB 16
__global__ __launch_bounds__(512) void proj_kernel(
        const float* __restrict__ feat,
        const float* __restrict__ intw) {
    int t = threadIdx.x;
    int o = t >> 4, d = t & 15;

    float w[NF];
    const float4* wp = reinterpret_cast<const float4*>(intw + (d * NF + o) * NF);
#pragma unroll
    for (int k = 0; k < NF / 4; k++) {
        float4 v = wp[k];
        w[4 * k + 0] = v.x; w[4 * k + 1] = v.y;
        w[4 * k + 2] = v.z; w[4 * k + 3] = v.w;
    }

    __shared__ __align__(16) float fshT[NF][20];   // feat transposed, padded
    __shared__ __align__(16) __half sstage[APB][SPAN];
    int a0 = blockIdx.x * APB;
    {
        int a = t >> 5, f = t & 31;
        fshT[f][a] = feat[(a0 + a) * NF + f];      // coalesced
    }
    __syncthreads();

    unsigned long long acc[8];                     // 8 f32x2 = 16 atoms
#pragma unroll
    for (int k = 0; k < 8; k++) acc[k] = 0ull;

#pragma unroll
    for (int f = 0; f < NF; f++) {
        U2 w2; w2.f = make_float2(w[f], w[f]);
        const float4* row = reinterpret_cast<const float4*>(fshT[f]);
#pragma unroll
        for (int q = 0; q < 4; q++) {
            F4U v; v.f4 = row[q];                  // broadcast LDS.128
            acc[2 * q + 0] = ffma2(w2.u, v.u[0], acc[2 * q + 0]);
            acc[2 * q + 1] = ffma2(w2.u, v.u[1], acc[2 * q + 1]);
        }
    }

    int pos = o * ND + d;                          // o-major position
#pragma unroll
    for (int k = 0; k < 8; k++) {
        U2 a; a.u = acc[k];
        sstage[2 * k + 0][pos] = __float2half_rn(a.f.x);
        sstage[2 * k + 1][pos] = __float2half_rn(a.f.y);
    }
    __syncthreads();

    // coalesced write-out: 16 atoms * 64 uint4 = 1024 uint4, 2 per thread
    const uint4* s4 = reinterpret_cast<const uint4*>(sstage);
    uint4* g4 = reinterpret_cast<uint4*>(g_projh) + a0 * (SPAN / 8);
#pragma unroll
    for (int k = 0; k < 2; k++)
        g4[k * 512 + t] = s4[k * 512 + t];
}

// ---------------- K2 (fused): per-atom warp does everything ------------------
// lane = o. Per pair: in-lane 16-d dot over fp16 proj row slice.
__global__ __launch_bounds__(256) void atom_kernel(
        const float* __restrict__ feat,
        const float* __restrict__ rhat,        // (P,4)
        const float* __restrict__ dist,
        const float* __restrict__ mu,
        const float* __restrict__ sigma,
        const int*   __restrict__ pair_first,  // sorted
        const int*   __restrict__ pair_second,
        const float* __restrict__ selfw,       // (32,32) [o][f]
        const float* __restrict__ selfb,
        const float* __restrict__ mixw,        // (64,32) k*32+oo, k=o*2+g
        const float* __restrict__ gnw,         // (64) [g*32+o]
        const float* __restrict__ gnb,
        float* __restrict__ out) {
    __shared__ float swsh[NF * NF];            // selfint_w transposed [f*32+o]
    __shared__ float xn_sh[8][64];

    for (int i = threadIdx.x; i < NF * NF; i += 256)
        swsh[i] = selfw[(i & 31) * NF + (i >> 5)];
    __syncthreads();

    int warp = threadIdx.x >> 5;
    int lane = threadIdx.x & 31;
    int a = blockIdx.x * 8 + warp;

    // segment search: lanes 0/1 find lower_bound(a), lower_bound(a+1)
    int target = a + (lane & 1);
    int lo = 0, hi = N_PAIRS;
    while (lo < hi) {
        int mid = (lo + hi) >> 1;
        if (pair_first[mid] < target) lo = mid + 1; else hi = mid;
    }
    int p0 = __shfl_sync(0xffffffffu, lo, 0);
    int p1 = __shfl_sync(0xffffffffu, lo, 1);

    float muL = (lane < ND) ? mu[lane] : 0.f;
    float sgL = (lane < ND) ? sigma[lane] : 1.f;

    float tf0 = 0.f, tf1 = 0.f, tf2 = 0.f, tf3 = 0.f;

    int j = (p0 < p1) ? pair_second[p0] : 0;   // prefetch
    for (int p = p0; p < p1; p++) {
        int jn = (p + 1 < p1) ? pair_second[p + 1] : 0;
        float dp = dist[p];                     // broadcast load

        // proj row slice for this lane: o = lane, 16 halves
        const uint4* pr = reinterpret_cast<const uint4*>(g_projh + j * SPAN);
        uint4 v0 = pr[2 * lane + 0];
        uint4 v1 = pr[2 * lane + 1];

        // sense in lanes<16
        float sv = 0.0f;
        {
            float invd = 1.0f / dp;
            float z    = (invd - muL) / sgL;
            float base = __expf(-0.5f * z * z);
            float c    = __cosf(0.24166097335f * dp);   // 0.5*pi/6.5
            float cut  = (dp < HARD_CUT) ? c * c : 0.0f;
            sv = base * cut;
        }

        const __half2* h0 = reinterpret_cast<const __half2*>(&v0);
        const __half2* h1 = reinterpret_cast<const __half2*>(&v1);
        float h = 0.f;
#pragma unroll
        for (int q = 0; q < 4; q++) {
            float2 c0 = __half22float2(h0[q]);
            float2 c1 = __half22float2(h1[q]);
            float sa = __shfl_sync(0xffffffffu, sv, 2 * q + 0);
            float sb = __shfl_sync(0xffffffffu, sv, 2 * q + 1);
            float sc = __shfl_sync(0xffffffffu, sv, 8 + 2 * q + 0);
            float sd = __shfl_sync(0xffffffffu, sv, 8 + 2 * q + 1);
            h = fmaf(sa, c0.x, h);
            h = fmaf(sb, c0.y, h);
            h = fmaf(sc, c1.x, h);
            h = fmaf(sd, c1.y, h);
        }

        const float4 r = *reinterpret_cast<const float4*>(rhat + p * NC);
        tf0 = fmaf(r.x, h, tf0);
        tf1 = fmaf(r.y, h, tf1);
        tf2 = fmaf(r.z, h, tf2);
        tf3 = fmaf(r.w, h, tf3);
        j = jn;
    }

    // invariants
    float inv0 = tf0;
    float inv1 = tf1 * tf1 + tf2 * tf2 + tf3 * tf3;

    // GroupNorm across lanes (channels)
    float xn0, xn1;
    {
        float s = inv0, sq = inv0 * inv0;
#pragma unroll
        for (int m = 16; m; m >>= 1) {
            s  += __shfl_xor_sync(0xffffffffu, s,  m);
            sq += __shfl_xor_sync(0xffffffffu, sq, m);
        }
        float mean = s * (1.0f / 32.0f);
        float var  = sq * (1.0f / 32.0f) - mean * mean;
        xn0 = (inv0 - mean) * rsqrtf(var + GN_EPS) * gnw[lane] + gnb[lane];
    }
    {
        float s = inv1, sq = inv1 * inv1;
#pragma unroll
        for (int m = 16; m; m >>= 1) {
            s  += __shfl_xor_sync(0xffffffffu, s,  m);
            sq += __shfl_xor_sync(0xffffffffu, sq, m);
        }
        float mean = s * (1.0f / 32.0f);
        float var  = sq * (1.0f / 32.0f) - mean * mean;
        xn1 = (inv1 - mean) * rsqrtf(var + GN_EPS) * gnw[NF + lane] + gnb[NF + lane];
    }
    xn_sh[warp][lane * 2 + 0] = xn0;   // k = o*2 + g
    xn_sh[warp][lane * 2 + 1] = xn1;
    __syncwarp();

    // mixing GEMV
    float m = 0.f;
#pragma unroll
    for (int k = 0; k < 2 * NF; k++)
        m = fmaf(xn_sh[warp][k], mixw[k * NF + lane], m);

    // self interaction
    float sp = selfb[lane];
    const float* fa = feat + a * NF;
#pragma unroll
    for (int f = 0; f < NF; f++)
        sp = fmaf(fa[f], swsh[f * NF + lane], sp);

    out[a * NF + lane] = m + sp;
}

// ---------------- launch ----------------------------------------------------
extern "C" void kernel_launch(void* const* d_in, const int* in_sizes, int n_in,
                              void* d_out, int out_size) {
    const float* in_features    = (const float*)d_in[0];
    const float* tensor_rhats   = (const float*)d_in[1];
    const float* dist_pairs     = (const float*)d_in[2];
    const float* int_weights    = (const float*)d_in[3];
    const float* selfint_w      = (const float*)d_in[4];
    const float* selfint_b      = (const float*)d_in[5];
    const float* mixing_weights = (const float*)d_in[6];
    const float* gn_weight      = (const float*)d_in[7];
    const float* gn_bias        = (const float*)d_in[8];
    const float* sens_mu        = (const float*)d_in[9];
    const float* sens_sigma     = (const float*)d_in[10];
    const int*   pair_first     = (const int*)d_in[11];
    const int*   pair_second    = (const int*)d_in[12];
    float* out = (float*)d_out;

    proj_kernel<<<N_ATOMS / APB, 512>>>(in_features, int_weights);
    atom_kernel<<<N_ATOMS / 8, 256>>>(in_features, tensor_rhats, dist_pairs,
                                      sens_mu, sens_sigma,
                                      pair_first, pair_second,
                                      selfint_w, selfint_b, mixing_weights,
                                      gn_weight, gn_bias, out);
}